// round 5
// baseline (speedup 1.0000x reference)
#include <cuda_runtime.h>
#include <math.h>

#ifndef M_PI
#define M_PI 3.14159265358979323846
#endif

// Two z-slices interleaved as float2. 4 y-band phases per slice-pair.
// Tile: 76 rows x 261 float2 (158.7 KB). Rows 0,1 zero guard; data rows
// 2..73 hold vol rows (64p-4)..(64p+67) clamped to [0,255] (others stay 0);
// rows 74,75 zero guard. Cols: 0,1 guard | 2..257 data | 258,259 guard | 260 pad.
// trow = floor(iy) - (64p-4) + 2, clamp [0,74]; tcol = floor(ix)+2, clamp [0,259].
#define TS    261
#define TROWS 76
#define TILE_BYTES (TROWS * TS * 8)

typedef unsigned long long ull;

#define FMA2(d,a,b,c) asm("fma.rn.f32x2 %0, %1, %2, %3;" : "=l"(d) : "l"(a), "l"(b), "l"(c))
#define ADD2(d,a,b)   asm("add.rn.f32x2 %0, %1, %2;"     : "=l"(d) : "l"(a), "l"(b))
#define PK2(d,lo,hi)  asm("mov.b64 %0, {%1, %2};"        : "=l"(d) : "f"(lo), "f"(hi))

__device__ int2   g_seg[4 * 4096];   // per (phase, view<<8|y): {xbeg, xend}
__device__ float4 g_ab[4096];        // per (view<<8|y): (A-0.5, B-0.5, A, B)

__global__ void fp_zero_kernel(float4* __restrict__ out, int n4) {
    int i = blockIdx.x * blockDim.x + threadIdx.x;
    if (i < n4) out[i] = make_float4(0.f, 0.f, 0.f, 0.f);
}

// z-independent line geometry, computed once.
__global__ void fp_range_kernel() {
    int i = blockIdx.x * 256 + threadIdx.x;   // (v<<8)|y
    int v = i >> 8, y = i & 255;
    float unit = (float)(M_PI / 16.0);
    float mu   = (float)(M_PI / 180.0);
    float a = __fadd_rn(mu, __fmul_rn((float)v, unit));
    double da = (double)a;
    float c = (float)cos(da), s = (float)sin(da);   // s > 0 for all views
    float yf = (float)y - 127.5f;
    float A = fmaf(-s, yf, fmaf(-c, 127.5f, 127.5f));  // ix = c*x + A
    float B = fmaf( c, yf, fmaf(-s, 127.5f, 127.5f));  // iy = s*x + B
    g_ab[i] = make_float4(A - 0.5f, B - 0.5f, A, B);

    float inv_s = __fdividef(1.f, s);
    float inv_c = __fdividef(1.f, c);
    float xa = (-1.f  - B) * inv_s;
    float xb = (256.f - B) * inv_s;
    float e0 = (-2.f  - A) * inv_c;
    float e1 = (258.f - A) * inv_c;
    float lo = fmaxf(xa, fminf(e0, e1));
    float hi = fminf(xb, fmaxf(e0, e1));
    int xlo = max(0,   (int)floorf(lo) - 2);
    int xhi = min(256, (int)ceilf(hi) + 3);
    if (xhi < xlo) xhi = xlo;

    int xs[5];
    xs[0] = xlo; xs[4] = xhi;
    int prev = xlo;
    for (int k = 1; k <= 3; k++) {
        float b = 64.f * (float)k - 0.5f;
        int t = (int)floorf((b - B) * inv_s) + 1;  // iy(t) >= b (±1 slack)
        t = min(max(t, prev), xhi);
        xs[k] = t; prev = t;
    }
    for (int p = 0; p < 4; p++)
        g_seg[p * 4096 + i] = make_int2(xs[p], xs[p + 1]);
}

extern __shared__ ull tile8[];

__global__ void __launch_bounds__(1024, 1)
fp_main_kernel(const float* __restrict__ vol, float* __restrict__ out)
{
    const int bx  = blockIdx.x;
    const int zp  = bx >> 3;          // z-pair 0..127
    const int p   = (bx >> 1) & 3;    // y-band phase
    const int vg  = bx & 1;           // view group of 8
    const int tid = threadIdx.x;

    __shared__ float s_c[16], s_s[16];
    if (tid < 16) {
        float unit = (float)(M_PI / 16.0);
        float mu   = (float)(M_PI / 180.0);
        float a = __fadd_rn(mu, __fmul_rn((float)tid, unit));
        double da = (double)a;
        s_c[tid] = (float)cos(da);
        s_s[tid] = (float)sin(da);
    }

    // zero whole tile, then overlay data rows
    for (int i = tid; i < TROWS * TS; i += 1024) tile8[i] = 0ULL;
    __syncthreads();

    const int vstart = 64 * p - 4;                 // tile data row 2 <-> vol row vstart
    const int r0 = max(0, vstart);
    const int r1 = min(255, vstart + 71);
    const int nrows = r1 - r0 + 1;
    const int rowoff = r0 - vstart + 2;            // tile row of vol row r0
    const float* __restrict__ v0 = vol + ((size_t)(zp << 1) << 16) + (r0 << 8);
    const float* __restrict__ v1 = v0 + 65536;
    float2* __restrict__ tile2 = (float2*)tile8;
    for (int i = tid; i < nrows * 64; i += 1024) {
        int r = i >> 6, c4 = (i & 63) << 2;
        float4 a = *(const float4*)(v0 + (r << 8) + c4);
        float4 b = *(const float4*)(v1 + (r << 8) + c4);
        float2* d = &tile2[(r + rowoff) * TS + 2 + c4];
        d[0] = make_float2(a.x, b.x);
        d[1] = make_float2(a.y, b.y);
        d[2] = make_float2(a.z, b.z);
        d[3] = make_float2(a.w, b.w);
    }
    __syncthreads();

    const int warp = tid >> 5, lane = tid & 31;

    // bit-domain clamps (magic float): tcol in [0,259], trow in [0,74]
    const int      LO_MIN = 0x4B400000 - 2,            LO_MAX = LO_MIN + 259;
    const int      HI_MIN = 0x4B400000 + 64 * p - 6,   HI_MAX = HI_MIN + 74;
    const unsigned UOFF   = (unsigned)HI_MIN * 261u + (unsigned)LO_MIN;

    const ull MAGIC2  = 0x4B4000004B400000ULL;
    const ull NMAGIC2 = 0xCB400000CB400000ULL;
    const ull NONE2   = 0xBF800000BF800000ULL;
    const ull STEP2   = 0x4200000042000000ULL;   // (32, 32)

    const int2*   __restrict__ segp = &g_seg[p * 4096];
    const float4* __restrict__ abp  = g_ab;

    for (int v8 = 0; v8 < 8; v8++) {
        const int v = v8 + (vg << 3);
        ull cs2; PK2(cs2, s_c[v], s_s[v]);
        const int vi = v << 8;

        for (int y = warp; y < 256; y += 32) {
            int2 seg = __ldg(&segp[vi + y]);
            const int xbeg = seg.x, xend = seg.y;
            if (xbeg >= xend) continue;

            float4 ab = __ldg(&abp[vi + y]);
            ull ab2, ab0, xf2;
            PK2(ab2, ab.x, ab.y);   // (A-0.5, B-0.5)
            PK2(ab0, ab.z, ab.w);   // (A, B)
            const float xf0 = (float)(xbeg + lane);
            PK2(xf2, xf0, xf0);
            const int nb = (xend - xbeg + 31) >> 5;
            const float xcut = (float)xend;
            ull acc2 = 0ULL;

#define FP_BODY(TAILMASK)                                                    \
            {                                                                \
                ull ih2, m2, f2, ixy2, w2;                                   \
                FMA2(ih2,  cs2, xf2, ab2);   /* (ix-.5, iy-.5) */            \
                FMA2(ixy2, cs2, xf2, ab0);   /* (ix, iy) */                  \
                ADD2(m2,  ih2, MAGIC2);                                      \
                ADD2(f2,  m2,  NMAGIC2);     /* (floor ix, floor iy) */      \
                FMA2(w2,  f2,  NONE2, ixy2); /* (wx, wy) */                  \
                int blo = (int)(unsigned)m2;                                 \
                int bhi = (int)(unsigned)(m2 >> 32);                         \
                blo = min(max(blo, LO_MIN), LO_MAX);                         \
                bhi = min(max(bhi, HI_MIN), HI_MAX);                         \
                unsigned idx = (unsigned)bhi * 261u + (unsigned)blo - UOFF;  \
                const ull* tp = tile8 + idx;                                 \
                ull V00 = tp[0], V01 = tp[1], V10 = tp[TS], V11 = tp[TS+1];  \
                float wx = __uint_as_float((unsigned)w2);                    \
                float wy = __uint_as_float((unsigned)(w2 >> 32));            \
                ull wx2, wy2; PK2(wx2, wx, wx); PK2(wy2, wy, wy);            \
                ull D01, D11, H0, H1, DH, VAL;                               \
                FMA2(D01, V00, NONE2, V01);  /* v01-v00 */                   \
                FMA2(D11, V10, NONE2, V11);                                  \
                FMA2(H0,  wx2, D01, V00);                                    \
                FMA2(H1,  wx2, D11, V10);                                    \
                FMA2(DH,  H0,  NONE2, H1);                                   \
                FMA2(VAL, wy2, DH,  H0);                                     \
                TAILMASK                                                     \
                ADD2(acc2, acc2, VAL);                                       \
                ADD2(xf2, xf2, STEP2);                                       \
            }

            for (int b = 0; b < nb - 1; b++) FP_BODY()
            FP_BODY(VAL = (__uint_as_float((unsigned)xf2) < xcut) ? VAL : 0ULL;)
#undef FP_BODY

            #pragma unroll
            for (int o = 16; o; o >>= 1) {
                ull other = __shfl_xor_sync(0xffffffffu, acc2, o);
                ADD2(acc2, acc2, other);
            }
            if (lane == 0) {
                int oidx = ((((zp << 1) << 8) + y) << 4) + v;
                atomicAdd(&out[oidx],        __uint_as_float((unsigned)acc2));
                atomicAdd(&out[oidx + 4096], __uint_as_float((unsigned)(acc2 >> 32)));
            }
        }
    }
}

extern "C" void kernel_launch(void* const* d_in, const int* in_sizes, int n_in,
                              void* d_out, int out_size) {
    (void)in_sizes; (void)n_in;
    cudaFuncSetAttribute(fp_main_kernel,
                         cudaFuncAttributeMaxDynamicSharedMemorySize, TILE_BYTES);
    fp_zero_kernel<<<512, 512>>>((float4*)d_out, out_size / 4);
    fp_range_kernel<<<16, 256>>>();
    fp_main_kernel<<<1024, 1024, TILE_BYTES>>>((const float*)d_in[0], (float*)d_out);
}

// round 6
// speedup vs baseline: 1.1482x; 1.1482x over previous
#include <cuda_runtime.h>
#include <math.h>

#ifndef M_PI
#define M_PI 3.14159265358979323846
#endif

// Overlapping half-slice tiles, clamp-to-zero guards.
// TS=263 chosen so per-view smem bank stride (TS*sin+cos mod 32) avoids
// small-gcd strides for ALL 16 views (<=2-way conflicts; TS=261 gave 8-way).
//   tile rows: 0,1 zero | 2..132 = 131 vol rows | 133,134 zero   (135 rows)
//   cols:      0,1 zero | 2..257 = vol cols 0..255 | 258..262 zero guard/pad
// Phase 0 holds vol rows 0..130   (serves floor(iy) in [-2, 131])
// Phase 1 holds vol rows 125..255 (serves floor(iy) in [123, 256])
// Lines split at integer xs (iy ~ 127.5 crossing): p0 takes x<xs, p1 x>=xs.
#define TS    263
#define TROWS 135
#define TILE_BYTES (TROWS * TS * 4)

typedef unsigned long long ull;

#define FMA2(d,a,b,c) asm("fma.rn.f32x2 %0, %1, %2, %3;" : "=l"(d) : "l"(a), "l"(b), "l"(c))
#define ADD2(d,a,b)   asm("add.rn.f32x2 %0, %1, %2;"     : "=l"(d) : "l"(a), "l"(b))
#define PK2(d,lo,hi)  asm("mov.b64 %0, {%1, %2};"        : "=l"(d) : "f"(lo), "f"(hi))

__device__ int2 g_ranges[4096];   // per (view<<8 | y): {xlo | xs<<16, xhi}

__global__ void fp_zero_kernel(float4* __restrict__ out, int n4) {
    int i = blockIdx.x * blockDim.x + threadIdx.x;
    if (i < n4) out[i] = make_float4(0.f, 0.f, 0.f, 0.f);
}

// z-independent line geometry, computed once.
__global__ void fp_range_kernel() {
    int i = blockIdx.x * 256 + threadIdx.x;   // 0..4095
    int v = i >> 8, y = i & 255;
    float unit = (float)(M_PI / 16.0);
    float mu   = (float)(M_PI / 180.0);
    float a = __fadd_rn(mu, __fmul_rn((float)v, unit));
    double da = (double)a;
    float c = (float)cos(da), s = (float)sin(da);   // s > 0 for all views
    float yf = (float)y - 127.5f;
    float A = fmaf(-s, yf, fmaf(-c, 127.5f, 127.5f));  // ix = c*x + A
    float B = fmaf( c, yf, fmaf(-s, 127.5f, 127.5f));  // iy = s*x + B
    float inv_s = __fdividef(1.f, s);
    float inv_c = __fdividef(1.f, c);
    float xa = (-1.f  - B) * inv_s;
    float xb = (256.f - B) * inv_s;
    float e0 = (-2.f  - A) * inv_c;
    float e1 = (258.f - A) * inv_c;
    float lo = fmaxf(xa, fminf(e0, e1));
    float hi = fminf(xb, fmaxf(e0, e1));
    int xlo = max(0,   (int)floorf(lo) - 2);
    int xhi = min(256, (int)ceilf(hi) + 3);
    if (xhi < xlo) xhi = xlo;
    int xs = (int)floorf((127.5f - B) * inv_s) + 1;   // iy(xs) >= 127.5 - ~1
    xs = min(max(xs, xlo), xhi);
    g_ranges[i] = make_int2(xlo | (xs << 16), xhi);
}

extern __shared__ float tile[];

__global__ void __launch_bounds__(1024, 1)
fp_main_kernel(const float* __restrict__ vol, float* __restrict__ out)
{
    const int bx  = blockIdx.x;
    const int z   = bx >> 2;
    const int p   = (bx >> 1) & 1;   // row-half phase
    const int vg  = bx & 1;          // view group of 8
    const int tid = threadIdx.x;

    __shared__ float s_c[16], s_s[16], s_Ac[16], s_Bc[16];
    if (tid < 16) {
        float unit = (float)(M_PI / 16.0);
        float mu   = (float)(M_PI / 180.0);
        float a = __fadd_rn(mu, __fmul_rn((float)tid, unit));
        double da = (double)a;
        float c = (float)cos(da), s = (float)sin(da);
        s_c[tid] = c; s_s[tid] = s;
        s_Ac[tid] = fmaf(-c, 127.5f, 127.5f);
        s_Bc[tid] = fmaf(-s, 127.5f, 127.5f);
    }

    // zero whole tile, then overlay 131 vol rows at tile rows 2..132
    for (int i = tid; i < TROWS * TS; i += 1024) tile[i] = 0.f;
    __syncthreads();

    const int rbase = p ? 123 : -2;   // trow = floor(iy) - rbase
    const float* __restrict__ vbase = vol + ((size_t)z << 16) + (p ? (125 * 256) : 0);
    for (int i = tid; i < 131 * 64; i += 1024) {
        int r = i >> 6, c4 = (i & 63) << 2;
        float4 v = *(const float4*)(vbase + (r << 8) + c4);
        float* d = &tile[(r + 2) * TS + 2 + c4];
        d[0] = v.x; d[1] = v.y; d[2] = v.z; d[3] = v.w;
    }
    __syncthreads();

    const int warp = tid >> 5, lane = tid & 31;

    // magic-float bit-domain clamps and index fold
    const int LO_MIN = 0x4B400000 - 2,     LO_MAX = 0x4B400000 + 257;
    const int HI_MIN = 0x4B400000 + rbase, HI_MAX = HI_MIN + 133;
    const unsigned UOFF = (unsigned)HI_MIN * (unsigned)TS + (unsigned)(0x4B400000 - 2);

    const ull MAGIC2  = 0x4B4000004B400000ULL;
    const ull NMAGIC2 = 0xCB400000CB400000ULL;
    const ull HALF2   = 0x3F0000003F000000ULL;
    const ull NONE2   = 0xBF800000BF800000ULL;
    const ull STEP2   = 0x4200000042000000ULL;  // (32, 32)

    for (int v8 = 0; v8 < 8; v8++) {
        const int v = v8 + (vg << 3);
        const float c = s_c[v], s = s_s[v], Ac = s_Ac[v], Bc = s_Bc[v];
        ull cs2; PK2(cs2, c, s);
        const int2* __restrict__ rp = &g_ranges[v << 8];

        for (int y = warp; y < 256; y += 32) {
            int2 d = __ldg(&rp[y]);
            const int xlo = d.x & 0xffff, xs = d.x >> 16, xhi = d.y;
            const int xbeg = p ? xs  : xlo;
            const int xend = p ? xhi : xs;
            if (xbeg >= xend) continue;

            const float yf = (float)y - 127.5f;
            const float A = fmaf(-s, yf, Ac) - 0.5f;
            const float B = fmaf( c, yf, Bc) - 0.5f;
            ull ab2, xf2;
            PK2(ab2, A, B);
            const float xf0 = (float)(xbeg + lane);
            PK2(xf2, xf0, xf0);
            const int nb = (xend - xbeg + 31) >> 5;
            const float xcut = (float)xend;
            float acc = 0.f;

#define FP_BODY(TAILMASK)                                                     \
            {                                                                 \
                ull ih2, m2, f2, wh2, w2;                                     \
                FMA2(ih2, cs2, xf2, ab2);      /* (ix-.5, iy-.5) */           \
                ADD2(m2,  ih2, MAGIC2);        /* magic round     */          \
                ADD2(f2,  m2,  NMAGIC2);       /* (floor ix, floor iy) */     \
                FMA2(wh2, f2,  NONE2, ih2);                                   \
                ADD2(w2,  wh2, HALF2);         /* (wx, wy) in [0,1] */        \
                int blo = (int)(unsigned)m2;                                  \
                int bhi = (int)(unsigned)(m2 >> 32);                          \
                blo = min(max(blo, LO_MIN), LO_MAX);                          \
                bhi = min(max(bhi, HI_MIN), HI_MAX);                          \
                unsigned idx = (unsigned)bhi * (unsigned)TS                   \
                             + (unsigned)blo - UOFF;                          \
                const float* tp = &tile[idx];                                 \
                float v00 = tp[0], v01 = tp[1], v10 = tp[TS], v11 = tp[TS+1]; \
                float wx = __uint_as_float((unsigned)w2);                     \
                float wy = __uint_as_float((unsigned)(w2 >> 32));             \
                float h0 = fmaf(wx, v01 - v00, v00);                          \
                float h1 = fmaf(wx, v11 - v10, v10);                          \
                float val = fmaf(wy, h1 - h0, h0);                            \
                TAILMASK                                                      \
                acc += val;                                                   \
                ADD2(xf2, xf2, STEP2);                                        \
            }

            for (int b = 0; b < nb - 1; b++) FP_BODY()
            FP_BODY(val = (__uint_as_float((unsigned)xf2) < xcut) ? val : 0.f;)
#undef FP_BODY

            #pragma unroll
            for (int o = 16; o; o >>= 1) acc += __shfl_xor_sync(0xffffffffu, acc, o);
            if (lane == 0) atomicAdd(&out[(((z << 8) + y) << 4) + v], acc);
        }
    }
}

extern "C" void kernel_launch(void* const* d_in, const int* in_sizes, int n_in,
                              void* d_out, int out_size) {
    (void)in_sizes; (void)n_in;
    cudaFuncSetAttribute(fp_main_kernel,
                         cudaFuncAttributeMaxDynamicSharedMemorySize, TILE_BYTES);
    fp_zero_kernel<<<512, 512>>>((float4*)d_out, out_size / 4);
    fp_range_kernel<<<16, 256>>>();
    fp_main_kernel<<<1024, 1024, TILE_BYTES>>>((const float*)d_in[0], (float*)d_out);
}

// round 8
// speedup vs baseline: 1.7721x; 1.5434x over previous
#include <cuda_runtime.h>
#include <cuda_fp16.h>
#include <math.h>

#ifndef M_PI
#define M_PI 3.14159265358979323846
#endif

// Two z-slices per tile element: half2(lo=z0, hi=z1). TS=263 (verified
// conflict-clean for all 16 view strides). Rows 0,1 zero | 2..132 = 131 vol
// rows | 133,134 zero. Cols 0,1 zero | 2..257 data | 258..262 zero/pad.
// Phase 0: vol rows 0..130; phase 1: vol rows 125..255. Lines split at
// integer xs (iy~127.5 crossing): p0 x<xs, p1 x>=xs.
#define TS    263
#define TROWS 135
#define TILE_BYTES (TROWS * TS * 4)

typedef unsigned long long ull;
typedef unsigned int uint;

#define FMA2(d,a,b,c) asm("fma.rn.f32x2 %0, %1, %2, %3;" : "=l"(d) : "l"(a), "l"(b), "l"(c))
#define ADD2(d,a,b)   asm("add.rn.f32x2 %0, %1, %2;"     : "=l"(d) : "l"(a), "l"(b))
#define PK2(d,lo,hi)  asm("mov.b64 %0, {%1, %2};"        : "=l"(d) : "f"(lo), "f"(hi))
// fp16x2 ops. PTX cvt.rn.f16x2.f32 d, a, b : a -> high half, b -> low half.
#define HSUB2(d,a,b)   asm("sub.rn.f16x2 %0, %1, %2;"        : "=r"(d) : "r"(a), "r"(b))
#define HFMA2(d,a,b,c) asm("fma.rn.f16x2 %0, %1, %2, %3;"    : "=r"(d) : "r"(a), "r"(b), "r"(c))
#define BCASTH(d,f)    asm("cvt.rn.f16x2.f32 %0, %1, %2;"    : "=r"(d) : "f"(f), "f"(f))
#define PACKH(d,lo,hi) asm("cvt.rn.f16x2.f32 %0, %1, %2;"    : "=r"(d) : "f"(hi), "f"(lo))
#define H2F2(f0,f1,v)  asm("{.reg .b16 l,h; mov.b32 {l,h}, %2; cvt.f32.f16 %0, l; cvt.f32.f16 %1, h;}" \
                           : "=f"(f0), "=f"(f1) : "r"(v))

__device__ int2 g_ranges[4096];   // per (view<<8 | y): {xlo | xs<<16, xhi}

__global__ void fp_zero_kernel(float4* __restrict__ out, int n4) {
    int i = blockIdx.x * blockDim.x + threadIdx.x;
    if (i < n4) out[i] = make_float4(0.f, 0.f, 0.f, 0.f);
}

// z-independent line geometry, computed once.
__global__ void fp_range_kernel() {
    int i = blockIdx.x * 256 + threadIdx.x;   // 0..4095
    int v = i >> 8, y = i & 255;
    float unit = (float)(M_PI / 16.0);
    float mu   = (float)(M_PI / 180.0);
    float a = __fadd_rn(mu, __fmul_rn((float)v, unit));
    double da = (double)a;
    float c = (float)cos(da), s = (float)sin(da);   // s > 0 for all views
    float yf = (float)y - 127.5f;
    float A = fmaf(-s, yf, fmaf(-c, 127.5f, 127.5f));  // ix = c*x + A
    float B = fmaf( c, yf, fmaf(-s, 127.5f, 127.5f));  // iy = s*x + B
    float inv_s = __fdividef(1.f, s);
    float inv_c = __fdividef(1.f, c);
    float xa = (-1.f  - B) * inv_s;
    float xb = (256.f - B) * inv_s;
    float e0 = (-2.f  - A) * inv_c;
    float e1 = (258.f - A) * inv_c;
    float lo = fmaxf(xa, fminf(e0, e1));
    float hi = fminf(xb, fmaxf(e0, e1));
    int xlo = max(0,   (int)floorf(lo) - 2);
    int xhi = min(256, (int)ceilf(hi) + 3);
    if (xhi < xlo) xhi = xlo;
    int xs = (int)floorf((127.5f - B) * inv_s) + 1;   // iy(xs) >= 127.5 - ~1
    xs = min(max(xs, xlo), xhi);
    g_ranges[i] = make_int2(xlo | (xs << 16), xhi);
}

extern __shared__ uint tileh[];   // half2 per element

__global__ void __launch_bounds__(1024, 1)
fp_main_kernel(const float* __restrict__ vol, float* __restrict__ out)
{
    const int bx  = blockIdx.x;
    const int zp  = bx >> 3;          // z-pair 0..127
    const int p   = (bx >> 2) & 1;    // row-half phase
    const int vg  = bx & 3;           // view group of 4
    const int tid = threadIdx.x;

    __shared__ float s_c[16], s_s[16], s_Ac[16], s_Bc[16];
    if (tid < 16) {
        float unit = (float)(M_PI / 16.0);
        float mu   = (float)(M_PI / 180.0);
        float a = __fadd_rn(mu, __fmul_rn((float)tid, unit));
        double da = (double)a;
        float c = (float)cos(da), s = (float)sin(da);
        s_c[tid] = c; s_s[tid] = s;
        s_Ac[tid] = fmaf(-c, 127.5f, 127.5f);
        s_Bc[tid] = fmaf(-s, 127.5f, 127.5f);
    }

    // zero whole tile, then overlay 131 vol rows at tile rows 2..132
    for (int i = tid; i < TROWS * TS; i += 1024) tileh[i] = 0u;
    __syncthreads();

    const int rbase = p ? 123 : -2;   // trow = floor(iy) - rbase
    const float* __restrict__ v0 = vol + ((size_t)(zp << 1) << 16) + (p ? (125 * 256) : 0);
    const float* __restrict__ v1 = v0 + 65536;
    for (int i = tid; i < 131 * 64; i += 1024) {
        int r = i >> 6, c4 = (i & 63) << 2;
        float4 a = *(const float4*)(v0 + (r << 8) + c4);
        float4 b = *(const float4*)(v1 + (r << 8) + c4);
        uint* d = &tileh[(r + 2) * TS + 2 + c4];
        uint h0, h1, h2, h3;
        PACKH(h0, a.x, b.x);
        PACKH(h1, a.y, b.y);
        PACKH(h2, a.z, b.z);
        PACKH(h3, a.w, b.w);
        d[0] = h0; d[1] = h1; d[2] = h2; d[3] = h3;
    }
    __syncthreads();

    const int warp = tid >> 5, lane = tid & 31;

    // magic-float bit-domain clamps and index fold (same as round 6)
    const int LO_MIN = 0x4B400000 - 2,     LO_MAX = 0x4B400000 + 257;
    const int HI_MIN = 0x4B400000 + rbase, HI_MAX = HI_MIN + 133;
    const unsigned UOFF = (unsigned)HI_MIN * (unsigned)TS + (unsigned)(0x4B400000 - 2);

    const ull MAGIC2  = 0x4B4000004B400000ULL;
    const ull NMAGIC2 = 0xCB400000CB400000ULL;
    const ull HALF2C  = 0x3F0000003F000000ULL;
    const ull NONE2   = 0xBF800000BF800000ULL;
    const ull STEP2   = 0x4200000042000000ULL;  // (32, 32)

    for (int v4 = 0; v4 < 4; v4++) {
        const int v = (vg << 2) + v4;
        const float c = s_c[v], s = s_s[v], Ac = s_Ac[v], Bc = s_Bc[v];
        ull cs2; PK2(cs2, c, s);
        const int2* __restrict__ rp = &g_ranges[v << 8];

        for (int y = warp; y < 256; y += 32) {
            int2 d = __ldg(&rp[y]);
            const int xlo = d.x & 0xffff, xs = d.x >> 16, xhi = d.y;
            const int xbeg = p ? xs  : xlo;
            const int xend = p ? xhi : xs;
            if (xbeg >= xend) continue;

            const float yf = (float)y - 127.5f;
            const float A = fmaf(-s, yf, Ac) - 0.5f;
            const float B = fmaf( c, yf, Bc) - 0.5f;
            ull ab2, xf2;
            PK2(ab2, A, B);
            const float xf0 = (float)(xbeg + lane);
            PK2(xf2, xf0, xf0);
            const int nb = (xend - xbeg + 31) >> 5;
            const float xcut = (float)xend;
            float acc0 = 0.f, acc1 = 0.f;

#define FP_BODY(TAILMASK)                                                     \
            {                                                                 \
                ull ih2, m2, f2, wh2, w2;                                     \
                FMA2(ih2, cs2, xf2, ab2);      /* (ix-.5, iy-.5) */           \
                ADD2(m2,  ih2, MAGIC2);                                       \
                ADD2(f2,  m2,  NMAGIC2);       /* (floor ix, floor iy) */     \
                FMA2(wh2, f2,  NONE2, ih2);                                   \
                ADD2(w2,  wh2, HALF2C);        /* (wx, wy) in [0,1] */        \
                int blo = (int)(unsigned)m2;                                  \
                int bhi = (int)(unsigned)(m2 >> 32);                          \
                blo = min(max(blo, LO_MIN), LO_MAX);                          \
                bhi = min(max(bhi, HI_MIN), HI_MAX);                          \
                unsigned idx = (unsigned)bhi * (unsigned)TS                   \
                             + (unsigned)blo - UOFF;                          \
                const uint* tp = &tileh[idx];                                 \
                uint V00 = tp[0], V01 = tp[1], V10 = tp[TS], V11 = tp[TS+1];  \
                float wx = __uint_as_float((unsigned)w2);                     \
                float wy = __uint_as_float((unsigned)(w2 >> 32));             \
                uint WX, WY; BCASTH(WX, wx); BCASTH(WY, wy);                  \
                uint D01, D11, H0, H1, DH, VAL;                               \
                HSUB2(D01, V01, V00);                                         \
                HSUB2(D11, V11, V10);                                         \
                HFMA2(H0, WX, D01, V00);                                      \
                HFMA2(H1, WX, D11, V10);                                      \
                HSUB2(DH, H1, H0);                                            \
                HFMA2(VAL, WY, DH, H0);                                       \
                TAILMASK                                                      \
                float f0, f1; H2F2(f0, f1, VAL);                              \
                acc0 += f0; acc1 += f1;                                       \
                ADD2(xf2, xf2, STEP2);                                        \
            }

            for (int b = 0; b < nb - 1; b++) FP_BODY()
            FP_BODY(VAL = (__uint_as_float((unsigned)xf2) < xcut) ? VAL : 0u;)
#undef FP_BODY

            #pragma unroll
            for (int o = 16; o; o >>= 1) {
                acc0 += __shfl_xor_sync(0xffffffffu, acc0, o);
                acc1 += __shfl_xor_sync(0xffffffffu, acc1, o);
            }
            if (lane == 0) {
                int oidx = ((((zp << 1) << 8) + y) << 4) + v;
                atomicAdd(&out[oidx],        acc0);
                atomicAdd(&out[oidx + 4096], acc1);
            }
        }
    }
}

extern "C" void kernel_launch(void* const* d_in, const int* in_sizes, int n_in,
                              void* d_out, int out_size) {
    (void)in_sizes; (void)n_in;
    cudaFuncSetAttribute(fp_main_kernel,
                         cudaFuncAttributeMaxDynamicSharedMemorySize, TILE_BYTES);
    fp_zero_kernel<<<512, 512>>>((float4*)d_out, out_size / 4);
    fp_range_kernel<<<16, 256>>>();
    fp_main_kernel<<<1024, 1024, TILE_BYTES>>>((const float*)d_in[0], (float*)d_out);
}